// round 6
// baseline (speedup 1.0000x reference)
#include <cuda_runtime.h>
#include <cuda_bf16.h>

#define BATCH      32
#define T_         3749          // num frames
#define CROW       3750          // chunks per row
#define NCHUNK     (BATCH*CROW)  // 120000
#define NBLK       148
#define NWARP      (NBLK*32)     // 4736
#define SILF       18
#define MINSP      6
#define WN32       120           // mask words (ceil(3749/32)=118, +pad)

__device__ float    g_S[NCHUNK];
__device__ unsigned g_count = 0;   // self-restoring: returns to 0 each launch
__device__ unsigned g_epoch = 0;   // monotonically grows across launches

// ---------------------------------------------------------------------------
// grid barrier: all NBLK blocks resident (grid == SM count, 1 CTA/SM).
// ---------------------------------------------------------------------------
__device__ __forceinline__ void grid_barrier() {
    __syncthreads();
    if (threadIdx.x == 0) {
        unsigned e0 = *((volatile unsigned*)&g_epoch);
        __threadfence();
        unsigned a = atomicAdd(&g_count, 1u);
        if (a == NBLK - 1) {
            g_count = 0;
            __threadfence();
            atomicAdd(&g_epoch, 1u);
        } else {
            while (*((volatile unsigned*)&g_epoch) == e0) { __nanosleep(64); }
        }
        __threadfence();
    }
    __syncthreads();
}

__device__ __forceinline__ int warp_incl_scan(int x, int lane) {
    #pragma unroll
    for (int o = 1; o < 32; o <<= 1) {
        int y = __shfl_up_sync(0xFFFFFFFFu, x, o);
        if (lane >= o) x += y;
    }
    return x;
}
// exclusive block scan over 1024 threads; safe for repeated use
__device__ __forceinline__ int block_excl_scan(int v, int lane, int wid, int* warp_sums) {
    int x = warp_incl_scan(v, lane);
    if (lane == 31) warp_sums[wid] = x;
    __syncthreads();
    if (wid == 0) {
        int ws = warp_sums[lane];
        int xx = warp_incl_scan(ws, lane);
        warp_sums[lane] = xx - ws;
    }
    __syncthreads();
    int res = warp_sums[wid] + x - v;
    __syncthreads();
    return res;
}

// any bit set in inclusive range [a,b] of packed 32-bit mask M; span <= 19 bits
__device__ __forceinline__ bool any_bit(const unsigned* M, int a, int b) {
    int wa = a >> 5, wb = b >> 5;
    unsigned ma = (~0u) << (a & 31);
    unsigned mb = (~0u) >> (31 - (b & 31));
    if (wa == wb) return (M[wa] & ma & mb) != 0u;
    return ((M[wa] & ma) | (M[wb] & mb)) != 0u;
}

// ---------------------------------------------------------------------------
// Fused persistent kernel.
// ---------------------------------------------------------------------------
__global__ __launch_bounds__(1024, 1)
void vad_fused_kernel(const float* __restrict__ W, float* __restrict__ out, int n_samples) {
    int tid = threadIdx.x, lane = tid & 31, wid = tid >> 5;

    // ===== Phase 1: chunk sums over all 148 blocks (HBM-bound) =====
    int gw = blockIdx.x * 32 + wid;
    for (int c = gw; c < NCHUNK; c += NWARP) {
        int r = c / CROW;
        int j = c - r * CROW;
        const float4* p = (const float4*)(W + (size_t)r * n_samples) + (size_t)j * 64;
        float4 a = __ldcs(p + lane);
        float4 b = __ldcs(p + lane + 32);
        float s = a.x*a.x + a.y*a.y + a.z*a.z + a.w*a.w
                + b.x*b.x + b.y*b.y + b.z*b.z + b.w*b.w;
        #pragma unroll
        for (int o = 16; o; o >>= 1) s += __shfl_down_sync(0xFFFFFFFFu, s, o);
        if (lane == 0) g_S[c] = s;
    }

    grid_barrier();

    // ===== Phase 2: per-row VAD on blocks 0..31 =====
    if (blockIdx.x >= BATCH) return;
    int b = blockIdx.x;

    __shared__ float    e_s[T_];
    __shared__ int      diff[CROW + 1];      // aliased as float S-stage first
    __shared__ int      hist_s[2048];
    __shared__ unsigned mword[WN32], lword[WN32];
    __shared__ int      warp_sums[32];
    __shared__ int      r_sh;
    __shared__ unsigned prefix_sh;
    __shared__ int      nzero_sh, cle_sh;
    __shared__ unsigned mingt_sh;
    __shared__ float    thr_sh;

    hist_s[tid] = 0; hist_s[tid + 1024] = 0;
    if (tid == 0) { nzero_sh = 0; cle_sh = 0; mingt_sh = 0xFFFFFFFFu; }

    // stage S row in diff's storage, then compute energies
    float* s_S = (float*)diff;
    const float* Srow = g_S + b * CROW;
    #pragma unroll
    for (int r = 0; r < 4; r++) { int i = r * 1024 + tid; if (i < CROW) s_S[i] = Srow[i]; }
    __syncthreads();
    #pragma unroll
    for (int r = 0; r < 4; r++) {
        int i = r * 1024 + tid;
        bool valid = i < T_;
        float e = 0.f;
        if (valid) { e = (s_S[i] + s_S[i + 1]) * (1.0f / 512.0f); e_s[i] = e; }
        unsigned bz = __ballot_sync(0xFFFFFFFFu, valid && e <= 0.f);
        if (lane == 0 && bz) atomicAdd(&nzero_sh, __popc(bz));
    }
    __syncthreads();

    int nzero = nzero_sh;
    int nz = T_ - nzero;
    float pos  = 0.2f * (float)(nz - 1);
    float flo  = floorf(pos);
    float frac = pos - flo;
    int ilo = min(max(nzero + (int)flo, 0), T_ - 1);
    int ihi = min(max(nzero + (int)ceilf(pos), 0), T_ - 1);

    // ---- pass 1: bits 31..22 (1024 bins) ----
    #pragma unroll
    for (int r = 0; r < 4; r++) {
        int i = r * 1024 + tid;
        bool ok = i < T_;
        unsigned k = ok ? __float_as_uint(e_s[i]) : 0u;
        int bin = ok ? (int)(k >> 22) : -1;
        unsigned grp = __match_any_sync(0xFFFFFFFFu, bin);
        if (ok && lane == __ffs(grp) - 1) atomicAdd(&hist_s[bin], __popc(grp));
    }
    __syncthreads();
    {
        int h = hist_s[tid]; hist_s[tid] = 0;   // own slot: read + re-zero
        int excl = block_excl_scan(h, lane, wid, warp_sums);
        if (ilo >= excl && ilo < excl + h) { r_sh = ilo - excl; prefix_sh = (unsigned)tid << 22; }
    }
    __syncthreads();
    unsigned prefix = prefix_sh;

    // ---- pass 2: bits 21..11 (2048 bins) ----
    #pragma unroll
    for (int r = 0; r < 4; r++) {
        int i = r * 1024 + tid;
        bool ok = i < T_;
        unsigned k = ok ? __float_as_uint(e_s[i]) : 0u;
        ok = ok && ((k & 0xFFC00000u) == prefix);
        int bin = ok ? (int)((k >> 11) & 2047u) : -1;
        unsigned grp = __match_any_sync(0xFFFFFFFFu, bin);
        if (ok && lane == __ffs(grp) - 1) atomicAdd(&hist_s[bin], __popc(grp));
    }
    __syncthreads();
    {
        int h0 = hist_s[2*tid], h1 = hist_s[2*tid + 1];
        hist_s[2*tid] = 0; hist_s[2*tid + 1] = 0;
        int rr = r_sh;
        int excl = block_excl_scan(h0 + h1, lane, wid, warp_sums);
        if (rr >= excl && rr < excl + h0)           { r_sh = rr - excl;      prefix_sh = prefix | ((unsigned)(2*tid)   << 11); }
        else if (rr >= excl + h0 && rr < excl + h0 + h1) { r_sh = rr - excl - h0; prefix_sh = prefix | ((unsigned)(2*tid+1) << 11); }
    }
    __syncthreads();
    prefix = prefix_sh;

    // ---- pass 3: bits 10..0 (2048 bins) ----
    #pragma unroll
    for (int r = 0; r < 4; r++) {
        int i = r * 1024 + tid;
        bool ok = i < T_;
        unsigned k = ok ? __float_as_uint(e_s[i]) : 0u;
        ok = ok && ((k & 0xFFFFF800u) == prefix);
        int bin = ok ? (int)(k & 2047u) : -1;
        unsigned grp = __match_any_sync(0xFFFFFFFFu, bin);
        if (ok && lane == __ffs(grp) - 1) atomicAdd(&hist_s[bin], __popc(grp));
    }
    __syncthreads();
    {
        int h0 = hist_s[2*tid], h1 = hist_s[2*tid + 1];
        int rr = r_sh;
        int excl = block_excl_scan(h0 + h1, lane, wid, warp_sums);
        if (rr >= excl && rr < excl + h0)                prefix_sh = prefix | (unsigned)(2*tid);
        else if (rr >= excl + h0 && rr < excl + h0 + h1) prefix_sh = prefix | (unsigned)(2*tid + 1);
    }
    __syncthreads();
    prefix = prefix_sh;
    float v_lo = __uint_as_float(prefix);

    // ---- rank ihi value: count(<= v_lo) and min of keys > v_lo ----
    {
        int cle = 0;
        unsigned mingt = 0xFFFFFFFFu;
        for (int i = tid; i < T_; i += 1024) {
            unsigned k = __float_as_uint(e_s[i]);
            if (k <= prefix) cle++;
            else mingt = min(mingt, k);
        }
        #pragma unroll
        for (int o = 16; o; o >>= 1) {
            cle  += __shfl_down_sync(0xFFFFFFFFu, cle, o);
            mingt = min(mingt, __shfl_down_sync(0xFFFFFFFFu, mingt, o));
        }
        if (lane == 0) {
            if (cle) atomicAdd(&cle_sh, cle);
            atomicMin(&mingt_sh, mingt);
        }
    }
    __syncthreads();
    if (tid == 0) {
        float v_hi = (cle_sh > ihi) ? v_lo : __uint_as_float(mingt_sh);
        float thr  = v_lo * (1.0f - frac) + v_hi * frac;
        thr_sh = (nz > 0) ? thr : 0.01f;
    }
    __syncthreads();
    float thr = thr_sh;

    // ---- packed mask via ballot; zero diff (s_S dead now) ----
    #pragma unroll
    for (int r = 0; r < 4; r++) {
        int i = r * 1024 + tid;
        bool pred = (i < T_) && (e_s[i] > thr);
        unsigned w = __ballot_sync(0xFFFFFFFFu, pred);
        if (lane == 0 && (i >> 5) < WN32) mword[i >> 5] = w;
    }
    for (int i = tid; i <= T_; i += 1024) diff[i] = 0;
    __syncthreads();

    // ---- last flags: bit t is group-last iff 1 at t and no 1 in (t, min(t+18,T-1)] ----
    #pragma unroll
    for (int r = 0; r < 4; r++) {
        int t = r * 1024 + tid;
        bool pred = false;
        if (t < T_ && ((mword[t >> 5] >> (t & 31)) & 1u)) {
            int a = t + 1, bnd = min(t + SILF, T_ - 1);
            pred = !(a <= bnd && any_bit(mword, a, bnd));
        }
        unsigned w = __ballot_sync(0xFFFFFFFFu, pred);
        if (lane == 0 && (t >> 5) < WN32) lword[t >> 5] = w;
    }
    __syncthreads();

    // ---- starts: no 1 in [t-18, t-1]; match to first last >= t ----
    for (int t = tid; t < T_; t += 1024) {
        if (!((mword[t >> 5] >> (t & 31)) & 1u)) continue;
        int a = max(t - SILF, 0), bnd = t - 1;
        if (a <= bnd && any_bit(mword, a, bnd)) continue;   // not a group start
        int w = t >> 5;
        unsigned cur = lword[w] & ((~0u) << (t & 31));
        while (cur == 0u) { w++; cur = lword[w]; }
        int l = (w << 5) + __ffs(cur) - 1;
        bool closed = (l + SILF <= T_ - 1);
        int end = closed ? l : T_;       // closed end excludes the last 1 (reference)
        if (end - t >= MINSP) { diff[t] = 1; diff[end] = -1; }
    }
    __syncthreads();

    // ---- inclusive prefix scan over diff, out = (cum > 0) as float ----
    int idx0 = tid * 4;
    int v[4];
    int s = 0;
    #pragma unroll
    for (int q = 0; q < 4; q++) {
        int ii = idx0 + q;
        int d = (ii < T_) ? diff[ii] : 0;
        s += d;
        v[q] = s;
    }
    int offset = block_excl_scan(s, lane, wid, warp_sums);
    float* orow = out + (size_t)b * T_;
    #pragma unroll
    for (int q = 0; q < 4; q++) {
        int ii = idx0 + q;
        if (ii < T_) orow[ii] = ((offset + v[q]) > 0) ? 1.0f : 0.0f;
    }
}

extern "C" void kernel_launch(void* const* d_in, const int* in_sizes, int n_in,
                              void* d_out, int out_size) {
    const float* W = (const float*)d_in[0];
    int n_samples = in_sizes[0] / BATCH;   // 960000
    vad_fused_kernel<<<NBLK, 1024>>>(W, (float*)d_out, n_samples);
}

// round 7
// speedup vs baseline: 1.0016x; 1.0016x over previous
#include <cuda_runtime.h>
#include <cuda_bf16.h>

#define BATCH  32
#define T_     3749            // num frames per row
#define CROW   3750            // chunks per row
#define NCHUNK (BATCH*CROW)    // 120000
#define NBLK   148
#define TILE   811             // ceil(NCHUNK/NBLK)
#define SILF   18
#define MINSP  6
#define WN32   120             // mask words (ceil(3749/32)=118, +pad)
#define HB1    4096            // pass-1 bins (top 12 bits)

__device__ float    g_E[BATCH * T_];
__device__ int      g_hist[BATCH * HB1];  // zero at load; phase 2 restores zeros
__device__ int      g_nzero[BATCH];       // zero at load; phase 2 restores zeros
__device__ unsigned g_count;              // returns to 0 every launch
__device__ unsigned g_epoch;              // grows across launches

// ---------------------------------------------------------------------------
// grid barrier: all NBLK blocks resident (grid == SM count, 1 CTA/SM).
// ---------------------------------------------------------------------------
__device__ __forceinline__ void grid_barrier() {
    __syncthreads();
    if (threadIdx.x == 0) {
        unsigned e0 = *((volatile unsigned*)&g_epoch);
        __threadfence();
        unsigned a = atomicAdd(&g_count, 1u);
        if (a == NBLK - 1) {
            g_count = 0;
            __threadfence();
            atomicAdd(&g_epoch, 1u);
        } else {
            while (*((volatile unsigned*)&g_epoch) == e0) { __nanosleep(32); }
        }
        __threadfence();
    }
    __syncthreads();
}

__device__ __forceinline__ int warp_incl_scan(int x, int lane) {
    #pragma unroll
    for (int o = 1; o < 32; o <<= 1) {
        int y = __shfl_up_sync(0xFFFFFFFFu, x, o);
        if (lane >= o) x += y;
    }
    return x;
}
// exclusive block scan over 1024 threads; safe for repeated use
__device__ __forceinline__ int block_excl_scan(int v, int lane, int wid, int* warp_sums) {
    int x = warp_incl_scan(v, lane);
    if (lane == 31) warp_sums[wid] = x;
    __syncthreads();
    if (wid == 0) {
        int ws = warp_sums[lane];
        int xx = warp_incl_scan(ws, lane);
        warp_sums[lane] = xx - ws;
    }
    __syncthreads();
    int res = warp_sums[wid] + x - v;
    __syncthreads();
    return res;
}

// any bit set in inclusive range [a,b] of packed 32-bit mask M; span <= 19 bits
__device__ __forceinline__ bool any_bit(const unsigned* M, int a, int b) {
    int wa = a >> 5, wb = b >> 5;
    unsigned ma = (~0u) << (a & 31);
    unsigned mb = (~0u) >> (31 - (b & 31));
    if (wa == wb) return (M[wa] & ma & mb) != 0u;
    return ((M[wa] & ma) | (M[wb] & mb)) != 0u;
}

// ---------------------------------------------------------------------------
// Fused persistent kernel.
// ---------------------------------------------------------------------------
__global__ __launch_bounds__(1024, 1)
void vad_fused_kernel(const float* __restrict__ W, float* __restrict__ out, int n_samples) {
    int tid = threadIdx.x, lane = tid & 31, wid = tid >> 5;

    __shared__ float    s_sum[TILE + 1];
    __shared__ float    e_s[T_];
    __shared__ int      diff[T_ + 2];
    __shared__ int      hist_s[1024];
    __shared__ unsigned mword[WN32], lword[WN32];
    __shared__ int      warp_sums[32];
    __shared__ int      r_sh;
    __shared__ unsigned prefix_sh;
    __shared__ int      cle_sh;
    __shared__ unsigned mingt_sh;
    __shared__ float    thr_sh;

    // ===== Phase 1: contiguous tile of chunk sums -> energies + hist + nzero =====
    int s0   = blockIdx.x * TILE;
    int len  = min(TILE, NCHUNK - s0);       // energies to attempt
    int nsum = min(len + 1, NCHUNK - s0);    // chunk sums needed (incl. halo)

    #pragma unroll 2
    for (int j = wid; j < nsum; j += 32) {
        int c = s0 + j;
        int r = c / CROW;
        int jj = c - r * CROW;
        const float4* p = (const float4*)(W + (size_t)r * n_samples) + (size_t)jj * 64;
        float4 a = __ldcs(p + lane);
        float4 b4 = __ldcs(p + lane + 32);
        float v = a.x*a.x + a.y*a.y + a.z*a.z + a.w*a.w
                + b4.x*b4.x + b4.y*b4.y + b4.z*b4.z + b4.w*b4.w;
        #pragma unroll
        for (int o = 16; o; o >>= 1) v += __shfl_down_sync(0xFFFFFFFFu, v, o);
        if (lane == 0) s_sum[j] = v;
    }
    __syncthreads();

    // one energy per thread (len <= 811 < 1024); whole warp executes match_any
    {
        int i = tid;
        bool ok = (i < len);
        int rowbin = -1;
        if (ok) {
            int t = s0 + i;
            int r = t / CROW;
            int tl = t - r * CROW;
            if (tl < CROW - 1) {
                float e = (s_sum[i] + s_sum[i + 1]) * (1.0f / 512.0f);
                g_E[r * T_ + tl] = e;
                if (e <= 0.0f) atomicAdd(&g_nzero[r], 1);
                rowbin = r * HB1 + (int)(__float_as_uint(e) >> 20);
            }
        }
        unsigned grp = __match_any_sync(0xFFFFFFFFu, rowbin);
        if (rowbin >= 0 && lane == __ffs(grp) - 1)
            atomicAdd(&g_hist[rowbin], __popc(grp));
    }

    grid_barrier();

    // ===== Phase 2: per-row VAD on blocks 0..31 =====
    if (blockIdx.x >= BATCH) return;
    int b = blockIdx.x;

    hist_s[tid] = 0;
    if (tid == 0) { cle_sh = 0; mingt_sh = 0xFFFFFFFFu; }

    const float* Erow = g_E + b * T_;
    #pragma unroll
    for (int r = 0; r < 4; r++) { int i = r * 1024 + tid; if (i < T_) e_s[i] = Erow[i]; }
    for (int i = tid; i <= T_; i += 1024) diff[i] = 0;
    int nzero = g_nzero[b];

    // pass-1 bins (4 per thread) + restore zeros
    int h4[4]; int base4 = tid << 2;
    #pragma unroll
    for (int j = 0; j < 4; j++) {
        h4[j] = g_hist[b * HB1 + base4 + j];
        g_hist[b * HB1 + base4 + j] = 0;
    }
    __syncthreads();
    if (tid == 0) g_nzero[b] = 0;   // restore after all reads

    int nz = T_ - nzero;
    float pos  = 0.2f * (float)(nz - 1);
    float flo  = floorf(pos);
    float frac = pos - flo;
    int ilo = min(max(nzero + (int)flo, 0), T_ - 1);
    int ihi = min(max(nzero + (int)ceilf(pos), 0), T_ - 1);

    // ---- pass 1: select top-12-bit bin from precomputed hist ----
    int tsum = h4[0] + h4[1] + h4[2] + h4[3];
    int texcl = block_excl_scan(tsum, lane, wid, warp_sums);
    {
        int cum = texcl;
        #pragma unroll
        for (int j = 0; j < 4; j++) {
            if (ilo >= cum && ilo < cum + h4[j]) { r_sh = ilo - cum; prefix_sh = (unsigned)(base4 + j) << 20; }
            cum += h4[j];
        }
    }
    __syncthreads();
    unsigned prefix = prefix_sh;

    // ---- pass 2: bits 19..10 ----
    #pragma unroll
    for (int r = 0; r < 4; r++) {
        int i = r * 1024 + tid;
        bool ok = i < T_;
        unsigned k = ok ? __float_as_uint(e_s[i]) : 0u;
        ok = ok && ((k & 0xFFF00000u) == prefix);
        int bin = ok ? (int)((k >> 10) & 1023u) : -1;
        unsigned grp = __match_any_sync(0xFFFFFFFFu, bin);
        if (ok && lane == __ffs(grp) - 1) atomicAdd(&hist_s[bin], __popc(grp));
    }
    __syncthreads();
    {
        int h = hist_s[tid]; hist_s[tid] = 0;   // own slot: read + re-zero
        int rr = r_sh;
        int excl = block_excl_scan(h, lane, wid, warp_sums);
        if (rr >= excl && rr < excl + h) { r_sh = rr - excl; prefix_sh = prefix | ((unsigned)tid << 10); }
    }
    __syncthreads();
    prefix = prefix_sh;

    // ---- pass 3: bits 9..0 ----
    #pragma unroll
    for (int r = 0; r < 4; r++) {
        int i = r * 1024 + tid;
        bool ok = i < T_;
        unsigned k = ok ? __float_as_uint(e_s[i]) : 0u;
        ok = ok && ((k & 0xFFFFFC00u) == prefix);
        int bin = ok ? (int)(k & 1023u) : -1;
        unsigned grp = __match_any_sync(0xFFFFFFFFu, bin);
        if (ok && lane == __ffs(grp) - 1) atomicAdd(&hist_s[bin], __popc(grp));
    }
    __syncthreads();
    {
        int h = hist_s[tid];
        int rr = r_sh;
        int excl = block_excl_scan(h, lane, wid, warp_sums);
        if (rr >= excl && rr < excl + h) prefix_sh = prefix | (unsigned)tid;
    }
    __syncthreads();
    prefix = prefix_sh;
    float v_lo = __uint_as_float(prefix);

    // ---- rank ihi value: count(<= v_lo) and min of keys > v_lo ----
    {
        int cle = 0;
        unsigned mingt = 0xFFFFFFFFu;
        for (int i = tid; i < T_; i += 1024) {
            unsigned k = __float_as_uint(e_s[i]);
            if (k <= prefix) cle++;
            else mingt = min(mingt, k);
        }
        #pragma unroll
        for (int o = 16; o; o >>= 1) {
            cle  += __shfl_down_sync(0xFFFFFFFFu, cle, o);
            mingt = min(mingt, __shfl_down_sync(0xFFFFFFFFu, mingt, o));
        }
        if (lane == 0) {
            if (cle) atomicAdd(&cle_sh, cle);
            atomicMin(&mingt_sh, mingt);
        }
    }
    __syncthreads();
    if (tid == 0) {
        float v_hi = (cle_sh > ihi) ? v_lo : __uint_as_float(mingt_sh);
        float thr  = v_lo * (1.0f - frac) + v_hi * frac;
        thr_sh = (nz > 0) ? thr : 0.01f;
    }
    __syncthreads();
    float thr = thr_sh;

    // ---- packed mask via ballot ----
    #pragma unroll
    for (int r = 0; r < 4; r++) {
        int i = r * 1024 + tid;
        bool pred = (i < T_) && (e_s[i] > thr);
        unsigned w = __ballot_sync(0xFFFFFFFFu, pred);
        if (lane == 0 && (i >> 5) < WN32) mword[i >> 5] = w;
    }
    __syncthreads();

    // ---- last flags: bit t is group-last iff 1 at t and no 1 in (t, min(t+18,T-1)] ----
    #pragma unroll
    for (int r = 0; r < 4; r++) {
        int t = r * 1024 + tid;
        bool pred = false;
        if (t < T_ && ((mword[t >> 5] >> (t & 31)) & 1u)) {
            int a = t + 1, bnd = min(t + SILF, T_ - 1);
            pred = !(a <= bnd && any_bit(mword, a, bnd));
        }
        unsigned w = __ballot_sync(0xFFFFFFFFu, pred);
        if (lane == 0 && (t >> 5) < WN32) lword[t >> 5] = w;
    }
    __syncthreads();

    // ---- starts: no 1 in [t-18, t-1]; match to first last >= t ----
    for (int t = tid; t < T_; t += 1024) {
        if (!((mword[t >> 5] >> (t & 31)) & 1u)) continue;
        int a = max(t - SILF, 0), bnd = t - 1;
        if (a <= bnd && any_bit(mword, a, bnd)) continue;   // not a group start
        int w = t >> 5;
        unsigned cur = lword[w] & ((~0u) << (t & 31));
        while (cur == 0u) { w++; cur = lword[w]; }
        int l = (w << 5) + __ffs(cur) - 1;
        bool closed = (l + SILF <= T_ - 1);
        int end = closed ? l : T_;       // closed end excludes the last 1 (reference)
        if (end - t >= MINSP) { diff[t] = 1; diff[end] = -1; }
    }
    __syncthreads();

    // ---- inclusive prefix scan over diff, out = (cum > 0) as float ----
    int idx0 = tid * 4;
    int v[4];
    int s = 0;
    #pragma unroll
    for (int q = 0; q < 4; q++) {
        int ii = idx0 + q;
        int d = (ii < T_) ? diff[ii] : 0;
        s += d;
        v[q] = s;
    }
    int offset = block_excl_scan(s, lane, wid, warp_sums);
    float* orow = out + (size_t)b * T_;
    #pragma unroll
    for (int q = 0; q < 4; q++) {
        int ii = idx0 + q;
        if (ii < T_) orow[ii] = ((offset + v[q]) > 0) ? 1.0f : 0.0f;
    }
}

extern "C" void kernel_launch(void* const* d_in, const int* in_sizes, int n_in,
                              void* d_out, int out_size) {
    const float* W = (const float*)d_in[0];
    int n_samples = in_sizes[0] / BATCH;   // 960000
    vad_fused_kernel<<<NBLK, 1024>>>(W, (float*)d_out, n_samples);
}

// round 8
// speedup vs baseline: 1.0694x; 1.0677x over previous
#include <cuda_runtime.h>
#include <cuda_bf16.h>

#define BATCH  32
#define T_     3749            // num frames per row
#define CROW   3750            // chunks per row
#define NCHUNK (BATCH*CROW)    // 120000
#define NBLK   148
#define TILE   811             // ceil(NCHUNK/NBLK)
#define SILF   18
#define MINSP  6
#define WN32   120             // mask words (ceil(3749/32)=118, +pad)
#define HB1    4096            // pass-1 bins (top 12 bits)
#define MAXG   256             // max groups per row (>= ceil(T/20))

__device__ float    g_E[BATCH * T_];
__device__ int      g_hist[BATCH * HB1];  // zero at load; phase 2 restores zeros
__device__ int      g_nzero[BATCH];       // zero at load; phase 2 restores zeros
__device__ unsigned g_count;              // returns to 0 every launch
__device__ unsigned g_epoch;              // grows across launches

__device__ __forceinline__ void grid_barrier() {
    __syncthreads();
    if (threadIdx.x == 0) {
        unsigned e0 = *((volatile unsigned*)&g_epoch);
        __threadfence();
        unsigned a = atomicAdd(&g_count, 1u);
        if (a == NBLK - 1) {
            g_count = 0;
            __threadfence();
            atomicAdd(&g_epoch, 1u);
        } else {
            while (*((volatile unsigned*)&g_epoch) == e0) { __nanosleep(32); }
        }
        __threadfence();
    }
    __syncthreads();
}

__device__ __forceinline__ int warp_incl_scan(int x, int lane) {
    #pragma unroll
    for (int o = 1; o < 32; o <<= 1) {
        int y = __shfl_up_sync(0xFFFFFFFFu, x, o);
        if (lane >= o) x += y;
    }
    return x;
}
// exclusive block scan over 1024 threads; safe for repeated use
__device__ __forceinline__ int block_excl_scan(int v, int lane, int wid, int* warp_sums) {
    int x = warp_incl_scan(v, lane);
    if (lane == 31) warp_sums[wid] = x;
    __syncthreads();
    if (wid == 0) {
        int ws = warp_sums[lane];
        int xx = warp_incl_scan(ws, lane);
        warp_sums[lane] = xx - ws;
    }
    __syncthreads();
    int res = warp_sums[wid] + x - v;
    __syncthreads();
    return res;
}

// any bit set in inclusive range [a,b] of packed 32-bit mask M; span <= 19 bits
__device__ __forceinline__ bool any_bit(const unsigned* M, int a, int b) {
    int wa = a >> 5, wb = b >> 5;
    unsigned ma = (~0u) << (a & 31);
    unsigned mb = (~0u) >> (31 - (b & 31));
    if (wa == wb) return (M[wa] & ma & mb) != 0u;
    return ((M[wa] & ma) | (M[wb] & mb)) != 0u;
}

__global__ __launch_bounds__(1024, 1)
void vad_fused_kernel(const float* __restrict__ W, float* __restrict__ out, int n_samples) {
    int tid = threadIdx.x, lane = tid & 31, wid = tid >> 5;

    __shared__ float    s_sum[TILE + 1];
    __shared__ float    e_s[T_];
    __shared__ int      diff[T_ + 2];
    __shared__ int      hist_s[1024];
    __shared__ unsigned mword[WN32], lword[WN32], sword[WN32];
    __shared__ int      woff[WN32];          // packed (soff | loff<<16)
    __shared__ short    llist[MAXG];
    __shared__ int      warp_sums[32];
    __shared__ int      r_sh;
    __shared__ unsigned prefix_sh;
    __shared__ int      cle_sh;
    __shared__ unsigned mingt_sh;
    __shared__ float    thr_sh;

    // ===== Phase 1: tile of chunk sums (software-pipelined) -> energies + hist + nzero =====
    int s0   = blockIdx.x * TILE;
    int len  = min(TILE, NCHUNK - s0);       // energies to attempt
    int nsum = min(len + 1, NCHUNK - s0);    // chunk sums needed (incl. halo)

    {
        int j = wid;
        float4 a0 = {0,0,0,0}, b0 = {0,0,0,0};
        if (j < nsum) {
            int c = s0 + j;
            int r = c / CROW, jj = c - r * CROW;
            const float4* p = (const float4*)(W + (size_t)r * n_samples) + (size_t)jj * 64;
            a0 = __ldcs(p + lane);
            b0 = __ldcs(p + lane + 32);
        }
        while (j < nsum) {
            int jn = j + 32;
            float4 a1 = {0,0,0,0}, b1 = {0,0,0,0};
            if (jn < nsum) {
                int c = s0 + jn;
                int r = c / CROW, jj = c - r * CROW;
                const float4* p = (const float4*)(W + (size_t)r * n_samples) + (size_t)jj * 64;
                a1 = __ldcs(p + lane);
                b1 = __ldcs(p + lane + 32);
            }
            float v = a0.x*a0.x + a0.y*a0.y + a0.z*a0.z + a0.w*a0.w
                    + b0.x*b0.x + b0.y*b0.y + b0.z*b0.z + b0.w*b0.w;
            #pragma unroll
            for (int o = 16; o; o >>= 1) v += __shfl_down_sync(0xFFFFFFFFu, v, o);
            if (lane == 0) s_sum[j] = v;
            a0 = a1; b0 = b1; j = jn;
        }
    }
    __syncthreads();

    // one energy per thread (len <= 811 < 1024); whole warp executes match_any
    {
        int i = tid;
        bool ok = (i < len);
        int rowbin = -1;
        if (ok) {
            int t = s0 + i;
            int r = t / CROW;
            int tl = t - r * CROW;
            if (tl < CROW - 1) {
                float e = (s_sum[i] + s_sum[i + 1]) * (1.0f / 512.0f);
                g_E[r * T_ + tl] = e;
                if (e <= 0.0f) atomicAdd(&g_nzero[r], 1);
                rowbin = r * HB1 + (int)(__float_as_uint(e) >> 20);
            }
        }
        unsigned grp = __match_any_sync(0xFFFFFFFFu, rowbin);
        if (rowbin >= 0 && lane == __ffs(grp) - 1)
            atomicAdd(&g_hist[rowbin], __popc(grp));
    }

    grid_barrier();

    // ===== Phase 2: per-row VAD on blocks 0..31 =====
    if (blockIdx.x >= BATCH) return;
    int b = blockIdx.x;

    hist_s[tid] = 0;
    if (tid == 0) { cle_sh = 0; mingt_sh = 0xFFFFFFFFu; }

    const float* Erow = g_E + b * T_;
    #pragma unroll
    for (int r = 0; r < 4; r++) { int i = r * 1024 + tid; if (i < T_) e_s[i] = Erow[i]; }
    for (int i = tid; i <= T_; i += 1024) diff[i] = 0;
    int nzero = g_nzero[b];

    // pass-1 bins (4 per thread) + restore zeros
    int h4[4]; int base4 = tid << 2;
    #pragma unroll
    for (int j = 0; j < 4; j++) {
        h4[j] = g_hist[b * HB1 + base4 + j];
        g_hist[b * HB1 + base4 + j] = 0;
    }
    __syncthreads();
    if (tid == 0) g_nzero[b] = 0;

    int nz = T_ - nzero;
    float pos  = 0.2f * (float)(nz - 1);
    float flo  = floorf(pos);
    float frac = pos - flo;
    int ilo = min(max(nzero + (int)flo, 0), T_ - 1);
    int ihi = min(max(nzero + (int)ceilf(pos), 0), T_ - 1);

    // ---- pass 1: select top-12-bit bin from precomputed hist ----
    int tsum = h4[0] + h4[1] + h4[2] + h4[3];
    int texcl = block_excl_scan(tsum, lane, wid, warp_sums);
    {
        int cum = texcl;
        #pragma unroll
        for (int j = 0; j < 4; j++) {
            if (ilo >= cum && ilo < cum + h4[j]) { r_sh = ilo - cum; prefix_sh = (unsigned)(base4 + j) << 20; }
            cum += h4[j];
        }
    }
    __syncthreads();
    unsigned prefix = prefix_sh;

    // ---- pass 2: bits 19..10 ----
    #pragma unroll
    for (int r = 0; r < 4; r++) {
        int i = r * 1024 + tid;
        bool ok = i < T_;
        unsigned k = ok ? __float_as_uint(e_s[i]) : 0u;
        ok = ok && ((k & 0xFFF00000u) == prefix);
        int bin = ok ? (int)((k >> 10) & 1023u) : -1;
        unsigned grp = __match_any_sync(0xFFFFFFFFu, bin);
        if (ok && lane == __ffs(grp) - 1) atomicAdd(&hist_s[bin], __popc(grp));
    }
    __syncthreads();
    {
        int h = hist_s[tid]; hist_s[tid] = 0;
        int rr = r_sh;
        int excl = block_excl_scan(h, lane, wid, warp_sums);
        if (rr >= excl && rr < excl + h) { r_sh = rr - excl; prefix_sh = prefix | ((unsigned)tid << 10); }
    }
    __syncthreads();
    prefix = prefix_sh;

    // ---- pass 3: bits 9..0 ----
    #pragma unroll
    for (int r = 0; r < 4; r++) {
        int i = r * 1024 + tid;
        bool ok = i < T_;
        unsigned k = ok ? __float_as_uint(e_s[i]) : 0u;
        ok = ok && ((k & 0xFFFFFC00u) == prefix);
        int bin = ok ? (int)(k & 1023u) : -1;
        unsigned grp = __match_any_sync(0xFFFFFFFFu, bin);
        if (ok && lane == __ffs(grp) - 1) atomicAdd(&hist_s[bin], __popc(grp));
    }
    __syncthreads();
    {
        int h = hist_s[tid];
        int rr = r_sh;
        int excl = block_excl_scan(h, lane, wid, warp_sums);
        if (rr >= excl && rr < excl + h) prefix_sh = prefix | (unsigned)tid;
    }
    __syncthreads();
    prefix = prefix_sh;
    float v_lo = __uint_as_float(prefix);

    // ---- rank ihi value: count(<= v_lo) and min of keys > v_lo ----
    {
        int cle = 0;
        unsigned mingt = 0xFFFFFFFFu;
        for (int i = tid; i < T_; i += 1024) {
            unsigned k = __float_as_uint(e_s[i]);
            if (k <= prefix) cle++;
            else mingt = min(mingt, k);
        }
        #pragma unroll
        for (int o = 16; o; o >>= 1) {
            cle  += __shfl_down_sync(0xFFFFFFFFu, cle, o);
            mingt = min(mingt, __shfl_down_sync(0xFFFFFFFFu, mingt, o));
        }
        if (lane == 0) {
            if (cle) atomicAdd(&cle_sh, cle);
            atomicMin(&mingt_sh, mingt);
        }
    }
    __syncthreads();
    if (tid == 0) {
        float v_hi = (cle_sh > ihi) ? v_lo : __uint_as_float(mingt_sh);
        float thr  = v_lo * (1.0f - frac) + v_hi * frac;
        thr_sh = (nz > 0) ? thr : 0.01f;
    }
    __syncthreads();
    float thr = thr_sh;

    // ---- packed mask via ballot ----
    #pragma unroll
    for (int r = 0; r < 4; r++) {
        int i = r * 1024 + tid;
        bool pred = (i < T_) && (e_s[i] > thr);
        unsigned w = __ballot_sync(0xFFFFFFFFu, pred);
        if (lane == 0 && (i >> 5) < WN32) mword[i >> 5] = w;
    }
    __syncthreads();

    // ---- start flags + last flags via ballot ----
    #pragma unroll
    for (int r = 0; r < 4; r++) {
        int t = r * 1024 + tid;
        bool one = (t < T_) && ((mword[t >> 5] >> (t & 31)) & 1u);
        bool iss = false, isl = false;
        if (one) {
            int a = max(t - SILF, 0), bnd = t - 1;
            iss = !(a <= bnd && any_bit(mword, a, bnd));
            a = t + 1; bnd = min(t + SILF, T_ - 1);
            isl = !(a <= bnd && any_bit(mword, a, bnd));
        }
        unsigned ws = __ballot_sync(0xFFFFFFFFu, iss);
        unsigned wl = __ballot_sync(0xFFFFFFFFu, isl);
        if (lane == 0 && (t >> 5) < WN32) { sword[t >> 5] = ws; lword[t >> 5] = wl; }
    }
    __syncthreads();

    // ---- ordinal offsets: packed (start_cnt | last_cnt<<16) exclusive scan over words ----
    {
        int v = 0;
        if (tid < WN32) {
            unsigned sw = sword[tid], lw = lword[tid];
            v = __popc(sw) | (__popc(lw) << 16);
        }
        int excl = block_excl_scan(v, lane, wid, warp_sums);
        if (tid < WN32) woff[tid] = excl;
    }
    __syncthreads();

    // ---- lasts write their position by ordinal ----
    #pragma unroll
    for (int r = 0; r < 4; r++) {
        int t = r * 1024 + tid;
        if (t < T_) {
            int w = t >> 5, bit = t & 31;
            if ((lword[w] >> bit) & 1u) {
                int rank = (woff[w] >> 16) + __popc(lword[w] & ((1u << bit) - 1u));
                llist[rank] = (short)t;
            }
        }
    }
    __syncthreads();

    // ---- starts: pair with same-ordinal last; mark diff ----
    #pragma unroll
    for (int r = 0; r < 4; r++) {
        int t = r * 1024 + tid;
        if (t < T_) {
            int w = t >> 5, bit = t & 31;
            if ((sword[w] >> bit) & 1u) {
                int rank = (woff[w] & 0xFFFF) + __popc(sword[w] & ((1u << bit) - 1u));
                int l = llist[rank];
                bool closed = (l + SILF <= T_ - 1);
                int end = closed ? l : T_;    // closed end excludes the last 1 (reference)
                if (end - t >= MINSP) { diff[t] = 1; diff[end] = -1; }
            }
        }
    }
    __syncthreads();

    // ---- inclusive prefix scan over diff, out = (cum > 0) as float ----
    int idx0 = tid * 4;
    int v[4];
    int s = 0;
    #pragma unroll
    for (int q = 0; q < 4; q++) {
        int ii = idx0 + q;
        int d = (ii < T_) ? diff[ii] : 0;
        s += d;
        v[q] = s;
    }
    int offset = block_excl_scan(s, lane, wid, warp_sums);
    float* orow = out + (size_t)b * T_;
    #pragma unroll
    for (int q = 0; q < 4; q++) {
        int ii = idx0 + q;
        if (ii < T_) orow[ii] = ((offset + v[q]) > 0) ? 1.0f : 0.0f;
    }
}

extern "C" void kernel_launch(void* const* d_in, const int* in_sizes, int n_in,
                              void* d_out, int out_size) {
    const float* W = (const float*)d_in[0];
    int n_samples = in_sizes[0] / BATCH;   // 960000
    vad_fused_kernel<<<NBLK, 1024>>>(W, (float*)d_out, n_samples);
}

// round 9
// speedup vs baseline: 1.1282x; 1.0549x over previous
#include <cuda_runtime.h>
#include <cuda_bf16.h>

#define BATCH  32
#define T_     3749            // num frames per row
#define CROW   3750            // chunks per row
#define NCHUNK (BATCH*CROW)    // 120000
#define NBLK   148
#define TILE   811             // ceil(NCHUNK/NBLK)
#define SILF   18
#define MINSP  6
#define WN32   120             // mask words storage (padded)
#define NWORDS 118             // ceil(3749/32)
#define HB1    4096            // pass-1 bins (top 12 bits)
#define MAXG   256

__device__ float    g_E[BATCH * T_];
__device__ int      g_hist[BATCH * HB1];  // zero at load; phase 2 restores zeros
__device__ int      g_nzero[BATCH];       // zero at load; phase 2 restores zeros
__device__ unsigned g_count;
__device__ unsigned g_epoch;

__device__ __forceinline__ void grid_barrier() {
    __syncthreads();
    if (threadIdx.x == 0) {
        unsigned e0 = *((volatile unsigned*)&g_epoch);
        __threadfence();
        unsigned a = atomicAdd(&g_count, 1u);
        if (a == NBLK - 1) {
            g_count = 0;
            __threadfence();
            atomicAdd(&g_epoch, 1u);
        } else {
            while (*((volatile unsigned*)&g_epoch) == e0) { __nanosleep(32); }
        }
        __threadfence();
    }
    __syncthreads();
}

__device__ __forceinline__ int warp_incl_scan(int x, int lane) {
    #pragma unroll
    for (int o = 1; o < 32; o <<= 1) {
        int y = __shfl_up_sync(0xFFFFFFFFu, x, o);
        if (lane >= o) x += y;
    }
    return x;
}
__device__ __forceinline__ int block_excl_scan(int v, int lane, int wid, int* warp_sums) {
    int x = warp_incl_scan(v, lane);
    if (lane == 31) warp_sums[wid] = x;
    __syncthreads();
    if (wid == 0) {
        int ws = warp_sums[lane];
        int xx = warp_incl_scan(ws, lane);
        warp_sums[lane] = xx - ws;
    }
    __syncthreads();
    int res = warp_sums[wid] + x - v;
    __syncthreads();
    return res;
}

__global__ __launch_bounds__(1024, 1)
void vad_fused_kernel(const float* __restrict__ W, float* __restrict__ out, int n_samples) {
    int tid = threadIdx.x, lane = tid & 31, wid = tid >> 5;

    __shared__ float    s_sum[TILE + 1];
    __shared__ int      diff[T_ + 2];
    __shared__ int      hist_s[1024];
    __shared__ unsigned mword[WN32], lword[WN32], sword[WN32];
    __shared__ int      woff[WN32];
    __shared__ short    llist[MAXG];
    __shared__ int      warp_sums[32];
    __shared__ int      r_sh;
    __shared__ unsigned prefix_sh;
    __shared__ int      cle_sh;
    __shared__ unsigned mingt_sh;
    __shared__ float    thr_sh;

    // ===== Phase 1 (unchanged from R8): pipelined chunk sums -> energies + hist + nzero =====
    int s0   = blockIdx.x * TILE;
    int len  = min(TILE, NCHUNK - s0);
    int nsum = min(len + 1, NCHUNK - s0);

    {
        int j = wid;
        float4 a0 = {0,0,0,0}, b0 = {0,0,0,0};
        if (j < nsum) {
            int c = s0 + j;
            int r = c / CROW, jj = c - r * CROW;
            const float4* p = (const float4*)(W + (size_t)r * n_samples) + (size_t)jj * 64;
            a0 = __ldcs(p + lane);
            b0 = __ldcs(p + lane + 32);
        }
        while (j < nsum) {
            int jn = j + 32;
            float4 a1 = {0,0,0,0}, b1 = {0,0,0,0};
            if (jn < nsum) {
                int c = s0 + jn;
                int r = c / CROW, jj = c - r * CROW;
                const float4* p = (const float4*)(W + (size_t)r * n_samples) + (size_t)jj * 64;
                a1 = __ldcs(p + lane);
                b1 = __ldcs(p + lane + 32);
            }
            float v = a0.x*a0.x + a0.y*a0.y + a0.z*a0.z + a0.w*a0.w
                    + b0.x*b0.x + b0.y*b0.y + b0.z*b0.z + b0.w*b0.w;
            #pragma unroll
            for (int o = 16; o; o >>= 1) v += __shfl_down_sync(0xFFFFFFFFu, v, o);
            if (lane == 0) s_sum[j] = v;
            a0 = a1; b0 = b1; j = jn;
        }
    }
    __syncthreads();

    {
        int i = tid;
        bool ok = (i < len);
        int rowbin = -1;
        if (ok) {
            int t = s0 + i;
            int r = t / CROW;
            int tl = t - r * CROW;
            if (tl < CROW - 1) {
                float e = (s_sum[i] + s_sum[i + 1]) * (1.0f / 512.0f);
                g_E[r * T_ + tl] = e;
                if (e <= 0.0f) atomicAdd(&g_nzero[r], 1);
                rowbin = r * HB1 + (int)(__float_as_uint(e) >> 20);
            }
        }
        unsigned grp = __match_any_sync(0xFFFFFFFFu, rowbin);
        if (rowbin >= 0 && lane == __ffs(grp) - 1)
            atomicAdd(&g_hist[rowbin], __popc(grp));
    }

    grid_barrier();

    // ===== Phase 2: per-row VAD, register-resident keys =====
    if (blockIdx.x >= BATCH) return;
    int b = blockIdx.x;

    hist_s[tid] = 0;
    if (tid == 0) { cle_sh = 0; mingt_sh = 0xFFFFFFFFu; }

    // all global loads issued together
    unsigned key[4]; bool kval[4];
    const float* Erow = g_E + b * T_;
    #pragma unroll
    for (int r = 0; r < 4; r++) {
        int i = r * 1024 + tid;
        kval[r] = (i < T_);
        key[r] = kval[r] ? __float_as_uint(Erow[i]) : 0u;
    }
    int nzero = g_nzero[b];
    int h4[4]; int base4 = tid << 2;
    #pragma unroll
    for (int j = 0; j < 4; j++) {
        h4[j] = g_hist[b * HB1 + base4 + j];
        g_hist[b * HB1 + base4 + j] = 0;
    }
    for (int i = tid; i <= T_; i += 1024) diff[i] = 0;
    __syncthreads();
    if (tid == 0) g_nzero[b] = 0;

    int nz = T_ - nzero;
    float pos  = 0.2f * (float)(nz - 1);
    float flo  = floorf(pos);
    float frac = pos - flo;
    int ilo = min(max(nzero + (int)flo, 0), T_ - 1);
    int ihi = min(max(nzero + (int)ceilf(pos), 0), T_ - 1);

    // ---- pass 1: top-12-bit bin from precomputed hist ----
    int tsum = h4[0] + h4[1] + h4[2] + h4[3];
    int texcl = block_excl_scan(tsum, lane, wid, warp_sums);
    {
        int cum = texcl;
        #pragma unroll
        for (int j = 0; j < 4; j++) {
            if (ilo >= cum && ilo < cum + h4[j]) { r_sh = ilo - cum; prefix_sh = (unsigned)(base4 + j) << 20; }
            cum += h4[j];
        }
    }
    __syncthreads();
    unsigned prefix = prefix_sh;

    // ---- pass 2: bits 19..10 (register keys) ----
    #pragma unroll
    for (int r = 0; r < 4; r++) {
        bool ok = kval[r] && ((key[r] & 0xFFF00000u) == prefix);
        int bin = ok ? (int)((key[r] >> 10) & 1023u) : -1;
        unsigned grp = __match_any_sync(0xFFFFFFFFu, bin);
        if (ok && lane == __ffs(grp) - 1) atomicAdd(&hist_s[bin], __popc(grp));
    }
    __syncthreads();
    {
        int h = hist_s[tid]; hist_s[tid] = 0;
        int rr = r_sh;
        int excl = block_excl_scan(h, lane, wid, warp_sums);
        if (rr >= excl && rr < excl + h) { r_sh = rr - excl; prefix_sh = prefix | ((unsigned)tid << 10); }
    }
    __syncthreads();
    prefix = prefix_sh;

    // ---- pass 3: bits 9..0 ----
    #pragma unroll
    for (int r = 0; r < 4; r++) {
        bool ok = kval[r] && ((key[r] & 0xFFFFFC00u) == prefix);
        int bin = ok ? (int)(key[r] & 1023u) : -1;
        unsigned grp = __match_any_sync(0xFFFFFFFFu, bin);
        if (ok && lane == __ffs(grp) - 1) atomicAdd(&hist_s[bin], __popc(grp));
    }
    __syncthreads();
    {
        int h = hist_s[tid];
        int rr = r_sh;
        int excl = block_excl_scan(h, lane, wid, warp_sums);
        if (rr >= excl && rr < excl + h) prefix_sh = prefix | (unsigned)tid;
    }
    __syncthreads();
    prefix = prefix_sh;
    float v_lo = __uint_as_float(prefix);

    // ---- rank ihi: count(<= v_lo), min key > v_lo (register keys) ----
    {
        int cle = 0;
        unsigned mingt = 0xFFFFFFFFu;
        #pragma unroll
        for (int r = 0; r < 4; r++) {
            if (kval[r]) {
                if (key[r] <= prefix) cle++;
                else mingt = min(mingt, key[r]);
            }
        }
        #pragma unroll
        for (int o = 16; o; o >>= 1) {
            cle  += __shfl_down_sync(0xFFFFFFFFu, cle, o);
            mingt = min(mingt, __shfl_down_sync(0xFFFFFFFFu, mingt, o));
        }
        if (lane == 0) {
            if (cle) atomicAdd(&cle_sh, cle);
            atomicMin(&mingt_sh, mingt);
        }
    }
    __syncthreads();
    if (tid == 0) {
        float v_hi = (cle_sh > ihi) ? v_lo : __uint_as_float(mingt_sh);
        float thr  = v_lo * (1.0f - frac) + v_hi * frac;
        thr_sh = (nz > 0) ? thr : 0.01f;
    }
    __syncthreads();
    float thr = thr_sh;

    // ---- mask ballot from register keys ----
    #pragma unroll
    for (int r = 0; r < 4; r++) {
        int i = r * 1024 + tid;
        bool pred = kval[r] && (__uint_as_float(key[r]) > thr);
        unsigned w = __ballot_sync(0xFFFFFFFFu, pred);
        if (lane == 0 && (i >> 5) < WN32) mword[i >> 5] = w;
    }
    __syncthreads();

    // ---- word-parallel start/last flags via 64-bit window-OR ----
    int cnt = 0;
    if (tid < NWORDS) {
        unsigned mp = tid ? mword[tid - 1] : 0u;
        unsigned mc = mword[tid];
        unsigned mn = mword[tid + 1];   // words 118/119 are zero
        // start: no 1 in previous 18 bits
        unsigned long long X = ((unsigned long long)mc << 32) | mp;
        unsigned long long z = (X << 1) | (X << 2);
        z |= z << 2; z |= z << 4; z |= z << 8;          // shifts 1..16
        z |= (X << 17) | (X << 18);                     // 1..18
        unsigned sw = mc & ~(unsigned)(z >> 32);
        // last: no 1 in next 18 bits
        unsigned long long Y = ((unsigned long long)mn << 32) | mc;
        unsigned long long q = (Y >> 1) | (Y >> 2);
        q |= q >> 2; q |= q >> 4; q |= q >> 8;
        q |= (Y >> 17) | (Y >> 18);
        unsigned lw = mc & ~(unsigned)q;
        sword[tid] = sw; lword[tid] = lw;
        cnt = __popc(sw) | (__popc(lw) << 16);
    }
    // ordinal offsets (packed start|last<<16)
    {
        int excl = block_excl_scan(cnt, lane, wid, warp_sums);
        if (tid < NWORDS) woff[tid] = excl;
    }
    __syncthreads();

    // lasts write positions by ordinal (sparse)
    if (tid < NWORDS) {
        unsigned lw = lword[tid];
        int rank = woff[tid] >> 16;
        int basep = tid << 5;
        while (lw) {
            int k = __ffs(lw) - 1; lw &= lw - 1u;
            llist[rank++] = (short)(basep + k);
        }
    }
    __syncthreads();

    // starts pair with same-ordinal last; mark diff (sparse)
    if (tid < NWORDS) {
        unsigned sw = sword[tid];
        int rank = woff[tid] & 0xFFFF;
        int basep = tid << 5;
        while (sw) {
            int k = __ffs(sw) - 1; sw &= sw - 1u;
            int t = basep + k;
            int l = llist[rank++];
            bool closed = (l + SILF <= T_ - 1);
            int end = closed ? l : T_;      // closed end excludes the last 1 (reference)
            if (end - t >= MINSP) { diff[t] = 1; diff[end] = -1; }
        }
    }
    __syncthreads();

    // ---- final scan over diff, out = (cum > 0) ----
    int idx0 = tid * 4;
    int v[4];
    int s = 0;
    #pragma unroll
    for (int q2 = 0; q2 < 4; q2++) {
        int ii = idx0 + q2;
        int d = (ii < T_) ? diff[ii] : 0;
        s += d;
        v[q2] = s;
    }
    int offset = block_excl_scan(s, lane, wid, warp_sums);
    float* orow = out + (size_t)b * T_;
    #pragma unroll
    for (int q2 = 0; q2 < 4; q2++) {
        int ii = idx0 + q2;
        if (ii < T_) orow[ii] = ((offset + v[q2]) > 0) ? 1.0f : 0.0f;
    }
}

extern "C" void kernel_launch(void* const* d_in, const int* in_sizes, int n_in,
                              void* d_out, int out_size) {
    const float* W = (const float*)d_in[0];
    int n_samples = in_sizes[0] / BATCH;   // 960000
    vad_fused_kernel<<<NBLK, 1024>>>(W, (float*)d_out, n_samples);
}

// round 10
// speedup vs baseline: 1.1961x; 1.0602x over previous
#include <cuda_runtime.h>
#include <cuda_bf16.h>

#define BATCH  32
#define T_     3749            // num frames per row
#define CROW   3750            // chunks per row
#define NCHUNK (BATCH*CROW)    // 120000
#define NBLK   148
#define TILE   811             // ceil(NCHUNK/NBLK)
#define SILF   18
#define MINSP  6
#define WN32   120             // mask words storage (padded)
#define NWORDS 118             // ceil(3749/32)
#define HB1    4096            // pass-1 bins (top 12 bits)
#define MAXG   256

__device__ float    g_E[BATCH * T_];
__device__ int      g_hist[BATCH * HB1];  // zero at load; phase 2 restores zeros
__device__ int      g_nzero[BATCH];       // zero at load; phase 2 restores zeros
__device__ unsigned g_count;
__device__ unsigned g_epoch;

__device__ __forceinline__ void grid_barrier() {
    __syncthreads();
    if (threadIdx.x == 0) {
        unsigned e0 = *((volatile unsigned*)&g_epoch);
        __threadfence();
        unsigned a = atomicAdd(&g_count, 1u);
        if (a == NBLK - 1) {
            g_count = 0;
            __threadfence();
            atomicAdd(&g_epoch, 1u);
        } else {
            while (*((volatile unsigned*)&g_epoch) == e0) { }
        }
        __threadfence();
    }
    __syncthreads();
}

__device__ __forceinline__ int warp_incl_scan(int x, int lane) {
    #pragma unroll
    for (int o = 1; o < 32; o <<= 1) {
        int y = __shfl_up_sync(0xFFFFFFFFu, x, o);
        if (lane >= o) x += y;
    }
    return x;
}
__device__ __forceinline__ int block_excl_scan(int v, int lane, int wid, int* warp_sums) {
    int x = warp_incl_scan(v, lane);
    if (lane == 31) warp_sums[wid] = x;
    __syncthreads();
    if (wid == 0) {
        int ws = warp_sums[lane];
        int xx = warp_incl_scan(ws, lane);
        warp_sums[lane] = xx - ws;
    }
    __syncthreads();
    int res = warp_sums[wid] + x - v;
    __syncthreads();
    return res;
}

__global__ __launch_bounds__(1024, 1)
void vad_fused_kernel(const float* __restrict__ W, float* __restrict__ out, int n_samples) {
    int tid = threadIdx.x, lane = tid & 31, wid = tid >> 5;

    __shared__ float    s_sum[TILE + 1];
    __shared__ int      hist_s[1024];
    __shared__ unsigned mword[WN32], lword[WN32], sword[WN32];
    __shared__ int      woff[WN32];
    __shared__ short    llist[MAXG];
    __shared__ short    vs_s[MAXG];
    __shared__ short    ve_s[MAXG];
    __shared__ int      warp_sums[32];
    __shared__ unsigned mg_w[32];
    __shared__ int      r_sh;
    __shared__ unsigned prefix_sh;
    __shared__ float    thr_sh;
    __shared__ int      G_sh;

    // ===== Phase 1: depth-3 pipelined chunk sums -> energies + hist + nzero =====
    int s0   = blockIdx.x * TILE;
    int len  = min(TILE, NCHUNK - s0);
    int nsum = min(len + 1, NCHUNK - s0);

    {
        float4 a0={0,0,0,0}, b0={0,0,0,0}, a1={0,0,0,0}, b1={0,0,0,0};
        int j = wid;
        if (j < nsum) {
            int c = s0 + j; int r = c / CROW, jj = c - r * CROW;
            const float4* p = (const float4*)(W + (size_t)r * n_samples) + (size_t)jj * 64;
            a0 = __ldcs(p + lane); b0 = __ldcs(p + lane + 32);
        }
        if (j + 32 < nsum) {
            int c = s0 + j + 32; int r = c / CROW, jj = c - r * CROW;
            const float4* p = (const float4*)(W + (size_t)r * n_samples) + (size_t)jj * 64;
            a1 = __ldcs(p + lane); b1 = __ldcs(p + lane + 32);
        }
        for (; j < nsum; j += 32) {
            float4 a2={0,0,0,0}, b2={0,0,0,0};
            if (j + 64 < nsum) {
                int c = s0 + j + 64; int r = c / CROW, jj = c - r * CROW;
                const float4* p = (const float4*)(W + (size_t)r * n_samples) + (size_t)jj * 64;
                a2 = __ldcs(p + lane); b2 = __ldcs(p + lane + 32);
            }
            float v = a0.x*a0.x + a0.y*a0.y + a0.z*a0.z + a0.w*a0.w
                    + b0.x*b0.x + b0.y*b0.y + b0.z*b0.z + b0.w*b0.w;
            #pragma unroll
            for (int o = 16; o; o >>= 1) v += __shfl_down_sync(0xFFFFFFFFu, v, o);
            if (lane == 0) s_sum[j] = v;
            a0 = a1; b0 = b1; a1 = a2; b1 = b2;
        }
    }
    __syncthreads();

    {
        int i = tid;
        bool ok = (i < len);
        int rowbin = -1;
        if (ok) {
            int t = s0 + i;
            int r = t / CROW;
            int tl = t - r * CROW;
            if (tl < CROW - 1) {
                float e = (s_sum[i] + s_sum[i + 1]) * (1.0f / 512.0f);
                g_E[r * T_ + tl] = e;
                if (e <= 0.0f) atomicAdd(&g_nzero[r], 1);
                rowbin = r * HB1 + (int)(__float_as_uint(e) >> 20);
            }
        }
        unsigned grp = __match_any_sync(0xFFFFFFFFu, rowbin);
        if (rowbin >= 0 && lane == __ffs(grp) - 1)
            atomicAdd(&g_hist[rowbin], __popc(grp));
    }

    grid_barrier();

    // ===== Phase 2: per-row VAD, register-resident keys =====
    if (blockIdx.x >= BATCH) return;
    int b = blockIdx.x;

    hist_s[tid] = 0;

    unsigned key[4]; bool kval[4];
    const float* Erow = g_E + b * T_;
    #pragma unroll
    for (int r = 0; r < 4; r++) {
        int i = r * 1024 + tid;
        kval[r] = (i < T_);
        key[r] = kval[r] ? __float_as_uint(Erow[i]) : 0u;
    }
    int nzero = g_nzero[b];
    int h4[4]; int base4 = tid << 2;
    #pragma unroll
    for (int j = 0; j < 4; j++) {
        h4[j] = g_hist[b * HB1 + base4 + j];
        g_hist[b * HB1 + base4 + j] = 0;
    }
    __syncthreads();
    if (tid == 0) g_nzero[b] = 0;

    int nz = T_ - nzero;
    float pos  = 0.2f * (float)(nz - 1);
    float flo  = floorf(pos);
    float frac = pos - flo;
    int ilo = min(max(nzero + (int)flo, 0), T_ - 1);
    int ihi = min(max(nzero + (int)ceilf(pos), 0), T_ - 1);

    // ---- pass 1: top-12-bit bin from precomputed hist ----
    int tsum = h4[0] + h4[1] + h4[2] + h4[3];
    int texcl = block_excl_scan(tsum, lane, wid, warp_sums);
    {
        int cum = texcl;
        #pragma unroll
        for (int j = 0; j < 4; j++) {
            if (ilo >= cum && ilo < cum + h4[j]) { r_sh = ilo - cum; prefix_sh = (unsigned)(base4 + j) << 20; }
            cum += h4[j];
        }
    }
    __syncthreads();
    unsigned prefix = prefix_sh;

    // ---- pass 2: bits 19..10 ----
    #pragma unroll
    for (int r = 0; r < 4; r++) {
        bool ok = kval[r] && ((key[r] & 0xFFF00000u) == prefix);
        int bin = ok ? (int)((key[r] >> 10) & 1023u) : -1;
        unsigned grp = __match_any_sync(0xFFFFFFFFu, bin);
        if (ok && lane == __ffs(grp) - 1) atomicAdd(&hist_s[bin], __popc(grp));
    }
    __syncthreads();
    {
        int h = hist_s[tid]; hist_s[tid] = 0;
        int rr = r_sh;
        int excl = block_excl_scan(h, lane, wid, warp_sums);
        if (rr >= excl && rr < excl + h) { r_sh = rr - excl; prefix_sh = prefix | ((unsigned)tid << 10); }
    }
    __syncthreads();
    prefix = prefix_sh;

    // ---- pass 3: bits 9..0 ----
    #pragma unroll
    for (int r = 0; r < 4; r++) {
        bool ok = kval[r] && ((key[r] & 0xFFFFFC00u) == prefix);
        int bin = ok ? (int)(key[r] & 1023u) : -1;
        unsigned grp = __match_any_sync(0xFFFFFFFFu, bin);
        if (ok && lane == __ffs(grp) - 1) atomicAdd(&hist_s[bin], __popc(grp));
    }
    __syncthreads();
    {
        int h = hist_s[tid];
        int rr = r_sh;
        int excl = block_excl_scan(h, lane, wid, warp_sums);
        if (rr >= excl && rr < excl + h) prefix_sh = prefix | (unsigned)tid;
    }
    __syncthreads();
    prefix = prefix_sh;
    float v_lo = __uint_as_float(prefix);

    // ---- cle/mingt via warp arrays (no same-address atomics) ----
    {
        int cle = 0;
        unsigned mingt = 0xFFFFFFFFu;
        #pragma unroll
        for (int r = 0; r < 4; r++) {
            if (kval[r]) {
                if (key[r] <= prefix) cle++;
                else mingt = min(mingt, key[r]);
            }
        }
        #pragma unroll
        for (int o = 16; o; o >>= 1) {
            cle  += __shfl_down_sync(0xFFFFFFFFu, cle, o);
            mingt = min(mingt, __shfl_down_sync(0xFFFFFFFFu, mingt, o));
        }
        if (lane == 0) { warp_sums[wid] = cle; mg_w[wid] = mingt; }
        __syncthreads();
        if (wid == 0) {
            int c = warp_sums[lane];
            unsigned m = mg_w[lane];
            #pragma unroll
            for (int o = 16; o; o >>= 1) {
                c += __shfl_down_sync(0xFFFFFFFFu, c, o);
                m = min(m, __shfl_down_sync(0xFFFFFFFFu, m, o));
            }
            if (lane == 0) {
                float v_hi = (c > ihi) ? v_lo : __uint_as_float(m);
                float thr  = v_lo * (1.0f - frac) + v_hi * frac;
                thr_sh = (nz > 0) ? thr : 0.01f;
            }
        }
        __syncthreads();
    }
    float thr = thr_sh;

    // ---- mask ballot from register keys ----
    #pragma unroll
    for (int r = 0; r < 4; r++) {
        int i = r * 1024 + tid;
        bool pred = kval[r] && (__uint_as_float(key[r]) > thr);
        unsigned w = __ballot_sync(0xFFFFFFFFu, pred);
        if (lane == 0 && (i >> 5) < WN32) mword[i >> 5] = w;
    }
    __syncthreads();

    // ---- word-parallel start/last flags via 64-bit window-OR ----
    int cnt = 0;
    if (tid < NWORDS) {
        unsigned mp = tid ? mword[tid - 1] : 0u;
        unsigned mc = mword[tid];
        unsigned mn = mword[tid + 1];   // words 118/119 are zero
        unsigned long long X = ((unsigned long long)mc << 32) | mp;
        unsigned long long z = (X << 1) | (X << 2);
        z |= z << 2; z |= z << 4; z |= z << 8;
        z |= (X << 17) | (X << 18);
        unsigned sw = mc & ~(unsigned)(z >> 32);
        unsigned long long Y = ((unsigned long long)mn << 32) | mc;
        unsigned long long q = (Y >> 1) | (Y >> 2);
        q |= q >> 2; q |= q >> 4; q |= q >> 8;
        q |= (Y >> 17) | (Y >> 18);
        unsigned lw = mc & ~(unsigned)q;
        sword[tid] = sw; lword[tid] = lw;
        cnt = __popc(sw) | (__popc(lw) << 16);
    }
    {
        int excl = block_excl_scan(cnt, lane, wid, warp_sums);
        if (tid < NWORDS) woff[tid] = excl;
        if (tid == NWORDS - 1) G_sh = (excl + cnt) & 0xFFFF;
    }
    __syncthreads();

    // lasts write positions by ordinal
    if (tid < NWORDS) {
        unsigned lw = lword[tid];
        int rank = woff[tid] >> 16;
        int basep = tid << 5;
        while (lw) {
            int k = __ffs(lw) - 1; lw &= lw - 1u;
            llist[rank++] = (short)(basep + k);
        }
    }
    __syncthreads();

    // starts pair with same-ordinal last; emit compact sorted intervals
    if (tid < NWORDS) {
        unsigned sw = sword[tid];
        int rank = woff[tid] & 0xFFFF;
        int basep = tid << 5;
        while (sw) {
            int k = __ffs(sw) - 1; sw &= sw - 1u;
            int t = basep + k;
            int l = llist[rank];
            bool closed = (l + SILF <= T_ - 1);
            int end = closed ? l : T_;      // closed end excludes the last 1 (reference)
            bool valid = (end - t >= MINSP);
            vs_s[rank] = (short)t;
            ve_s[rank] = (short)(valid ? end : t);   // empty interval if invalid
            rank++;
        }
    }
    __syncthreads();

    // ---- output: position covered iff inside interval found by binary search ----
    int G = G_sh;
    float* orow = out + (size_t)b * T_;
    #pragma unroll
    for (int r = 0; r < 4; r++) {
        int p = r * 1024 + tid;
        if (p < T_) {
            float o = 0.0f;
            if (G > 0) {
                // last g with vs[g] <= p
                int lo = 0, hi = G - 1;
                if ((int)vs_s[0] <= p) {
                    while (lo < hi) {
                        int mid = (lo + hi + 1) >> 1;
                        if ((int)vs_s[mid] <= p) lo = mid; else hi = mid - 1;
                    }
                    if (p < (int)ve_s[lo]) o = 1.0f;
                }
            }
            orow[p] = o;
        }
    }
}

extern "C" void kernel_launch(void* const* d_in, const int* in_sizes, int n_in,
                              void* d_out, int out_size) {
    const float* W = (const float*)d_in[0];
    int n_samples = in_sizes[0] / BATCH;   // 960000
    vad_fused_kernel<<<NBLK, 1024>>>(W, (float*)d_out, n_samples);
}